// round 13
// baseline (speedup 1.0000x reference)
#include <cuda_runtime.h>
#include <cuda_fp16.h>

// LearnableShiftViews: out[v,b,c,h,w] = separable bilinear resample of x[b,c]
// at pix = (idx + d)*size/(size-1) - 0.5 per axis, zero padding.
//
// R13 (base = R12, 49.2us, L1-bound at 79% with tap-LDS = 2.0 cyc/group):
// row-pair sharing. Each thread-pass computes TWO adjacent output rows
// (2p, 2p+1) of a view from THREE unconditionally-loaded staged rows
// (a, a+1, a+2): out0 = blend(v0,v1), out1 = blend(v1,v2), sharing the
// middle x-lerp. Valid when the iy0 step between the rows is 1 (all but
// ~0.45% of rows) and no top-edge clamp; the ycoef builder detects the
// exceptions and a tiny epilogue recomputes those rows exactly and
// overwrites. Staged table has a zero TOP pad row and two zero BOTTOM pad
// rows so speculative third-row reads are finite and mask-consistent.
// Data path: skewed fp16 diff-pair table (entry p = half2(a0, a1-a0)),
// quad-x mapping, STG.128. Weights/blend fp32.

namespace {

constexpr int H = 224;
constexpr int W = 224;
constexpr int B = 64;
constexpr int C = 3;
constexpr int BCN = B * C;     // 192
constexpr int V = 5;
constexpr int TILE_Y = 16;     // 8 row-pairs
constexpr int NPAIR = TILE_Y / 2;
constexpr int ROWS_CAP = 20;   // data rows; +3 pad rows (1 top, 2 bottom)
constexpr int NTHREADS = 224;  // 56 quads x 4 pair-bands x 2 pair-passes
constexpr int CH4 = W / 4;     // 56 float4 chunks per input row
constexpr int SRS = 236;       // skewed words per packed row
constexpr int SRS4 = SRS * 4;  // row stride in bytes

__device__ __forceinline__ int skew(int e) { return e + (e >> 5); }

__global__ __launch_bounds__(NTHREADS)
void shift_views_kernel(const float* __restrict__ x,
                        const float* __restrict__ offs,
                        float* __restrict__ out) {
    __shared__ __half2 spack[(ROWS_CAP + 3) * SRS];  // pad + data + 2 pads, 21.7 KB
    __shared__ float4  ycA[V][NPAIR];    // {wy00, wy10, wy01, wy11}
    __shared__ int     ycB[V][NPAIR];    // byte offset of staged row a
    __shared__ int     nfix;
    __shared__ int     fixlist[64];      // (v<<8)|pair

    const int yb  = blockIdx.x * TILE_Y;
    const int bc  = blockIdx.y;
    const int tid = threadIdx.x;
    const float sy = (float)H / (float)(H - 1);
    const float sx = (float)W / (float)(W - 1);

    // ---- Row range needed across all views (endpoints suffice; monotone).
    int rmin = H - 1, rmax = 0;
#pragma unroll
    for (int v = 0; v < V; ++v) {
        float dy = __ldg(&offs[2 * v]);
        int lo = (int)floorf(((float)yb + dy) * sy - 0.5f);
        int hi = (int)floorf(((float)(yb + TILE_Y - 1) + dy) * sy - 0.5f) + 1;
        lo = max(lo, 0);
        hi = min(hi, H - 1);
        rmin = min(rmin, lo);
        rmax = max(rmax, hi);
    }
    if (rmin > rmax) { rmin = 0; rmax = 0; }
    rmax = min(rmax, rmin + ROWS_CAP - 1);
    const int nrows = rmax - rmin + 1;   // data rows staged at index 1..nrows

    if (tid == 0) nfix = 0;
    __syncthreads();

    // ---- Build pair-coefficient tables: one thread per (v, pair).
    if (tid < V * NPAIR) {
        int v = tid >> 3;
        int p = tid & 7;
        float dy = offs[2 * v];

        float yp0 = ((float)(yb + 2 * p) + dy) * sy - 0.5f;
        float pf0 = floorf(yp0);
        float fy0 = yp0 - pf0;
        int   i0  = (int)pf0;
        float w00 = ((unsigned)i0       < (unsigned)H) ? (1.0f - fy0) : 0.0f;
        float w10 = ((unsigned)(i0 + 1) < (unsigned)H) ? fy0          : 0.0f;

        float yp1 = ((float)(yb + 2 * p + 1) + dy) * sy - 0.5f;
        float pf1 = floorf(yp1);
        float fy1 = yp1 - pf1;
        int   i1  = (int)pf1;
        float w01 = ((unsigned)i1       < (unsigned)H) ? (1.0f - fy1) : 0.0f;
        float w11 = ((unsigned)(i1 + 1) < (unsigned)H) ? fy1          : 0.0f;

        int pa_u = i0 - rmin + 1;                 // staged index (1-based data)
        int s    = i1 - i0;
        int pa   = min(max(pa_u, 0), nrows);
        ycA[v][p] = make_float4(w00, w10, w01, w11);
        ycB[v][p] = pa * SRS4;
        if (pa_u != pa || s != 1) {               // main-path assumption broken
            int k = atomicAdd(&nfix, 1);
            if (k < 64) fixlist[k] = (v << 8) | p;
        }
    }

    // ---- Zero pad rows: 0 (top), nrows+1, nrows+2 (bottom).
    for (int i = tid; i < 3 * SRS; i += NTHREADS) {
        int w  = i / SRS;
        int rr = (w == 0) ? 0 : (nrows + w);
        spack[rr * SRS + (i - w * SRS)] = __floats2half2_rn(0.f, 0.f);
    }

    // ---- Stage + pack skewed diff table into rows 1..nrows.
    {
        const float*  srcf = x + (size_t)bc * (H * W) + (size_t)rmin * W;
        const float4* src4 = reinterpret_cast<const float4*>(srcf);
        const int total = nrows * CH4;
        for (int i = tid; i < total; i += NTHREADS) {
            int r = i / CH4;
            int c = i - r * CH4;
            float4 g = src4[r * CH4 + c];
            float hi3 = (c == CH4 - 1) ? 0.0f : __ldg(srcf + r * W + 4 * c + 4);
            __half2* row = &spack[(r + 1) * SRS];
            row[skew(4 * c + 2)] = __floats2half2_rn(g.x, g.y - g.x);
            row[skew(4 * c + 3)] = __floats2half2_rn(g.y, g.z - g.y);
            row[skew(4 * c + 4)] = __floats2half2_rn(g.z, g.w - g.z);
            row[skew(4 * c + 5)] = __floats2half2_rn(g.w, hi3 - g.w);
            if (c == 0) {                 // left pads: (0,0) and (0, data[0])
                row[skew(0)] = __floats2half2_rn(0.f, 0.f);
                row[skew(1)] = __floats2half2_rn(0.f, g.x);
            }
            if (c == CH4 - 1) {           // right pad (clamp target)
                row[skew(226)] = __floats2half2_rn(0.f, 0.f);
            }
        }
    }
    __syncthreads();

    // ---- Main loop: thread = (pair-band r, quad q); per pass computes the
    // row pair (2p, 2p+1) from 3 staged rows; 2x STG.128.
    const int r  = tid / 56;     // 0..3
    const int q  = tid - r * 56; // 0..55
    const int x0 = 4 * q;
    const char* sb = (const char*)spack;

#pragma unroll 1
    for (int v = 0; v < V; ++v) {
        const float dx = __ldg(&offs[2 * v + 1]);
        const float cx = dx * sx - 0.5f;

        float fxj[4];
        int   saj[4];
#pragma unroll
        for (int j = 0; j < 4; ++j) {
            float xpix = fmaf((float)(x0 + j), sx, cx);
            int   ix0  = __float2int_rd(xpix);
            fxj[j]     = xpix - (float)ix0;
            int   p0   = min(max(ix0 + 2, 0), 226);
            saj[j]     = skew(p0) * 4;
        }

        float* __restrict__ vbase =
            out + (((size_t)(v * BCN + bc)) * H + yb) * W + x0;

#pragma unroll
        for (int pp = 0; pp < 2; ++pp) {
            const int p  = r + 4 * pp;           // pair index 0..7
            float4 wv    = ycA[v][p];
            const char* rb = sb + ycB[v][p];

            float4 res0, res1;
            float* r0p = &res0.x;
            float* r1p = &res1.x;
#pragma unroll
            for (int j = 0; j < 4; ++j) {
                const char* a = rb + saj[j];
                __half2 h0 = *(const __half2*)(a);
                __half2 h1 = *(const __half2*)(a + SRS4);
                __half2 h2 = *(const __half2*)(a + 2 * SRS4);
                float t0 = fmaf(fxj[j], __high2float(h0), __low2float(h0));
                float t1 = fmaf(fxj[j], __high2float(h1), __low2float(h1));
                float t2 = fmaf(fxj[j], __high2float(h2), __low2float(h2));
                r0p[j] = fmaf(t1, wv.y, t0 * wv.x);   // rows (a, a+1)
                r1p[j] = fmaf(t2, wv.w, t1 * wv.z);   // rows (a+1, a+2)
            }
            *reinterpret_cast<float4*>(vbase + (size_t)(2 * p) * W)     = res0;
            *reinterpret_cast<float4*>(vbase + (size_t)(2 * p + 1) * W) = res1;
        }
    }
    __syncthreads();

    // ---- Fixup epilogue: recompute both rows of each anomalous (v, pair)
    // with the exact general path and overwrite. Rare (<= ~1 per view-tile).
    const int nf = min(nfix, 64);
    for (int k = 0; k < nf; ++k) {
        int e = fixlist[k];
        int v = e >> 8;
        int p = e & 255;
        float dy = offs[2 * v];
        float dx = offs[2 * v + 1];

        // x-coefficients for x = tid
        float xpix = fmaf((float)tid, sx, dx * sx - 0.5f);
        int   ix0  = __float2int_rd(xpix);
        float fx   = xpix - (float)ix0;
        int   sa   = skew(min(max(ix0 + 2, 0), 226)) * 4;

#pragma unroll
        for (int rr = 0; rr < 2; ++rr) {
            int   ty   = 2 * p + rr;
            float ypix = ((float)(yb + ty) + dy) * sy - 0.5f;
            float py   = floorf(ypix);
            float fy   = ypix - py;
            int   iy0  = (int)py;
            float wy0  = ((unsigned)iy0       < (unsigned)H) ? (1.0f - fy) : 0.0f;
            float wy1  = ((unsigned)(iy0 + 1) < (unsigned)H) ? fy          : 0.0f;
            int r0s = min(max(iy0     - rmin + 1, 0), nrows + 2);
            int r1s = min(max(iy0 + 1 - rmin + 1, 0), nrows + 2);
            __half2 h0 = *(const __half2*)(sb + r0s * SRS4 + sa);
            __half2 h1 = *(const __half2*)(sb + r1s * SRS4 + sa);
            float t0 = fmaf(fx, __high2float(h0), __low2float(h0));
            float t1 = fmaf(fx, __high2float(h1), __low2float(h1));
            out[(((size_t)(v * BCN + bc)) * H + yb + ty) * W + tid] =
                fmaf(t1, wy1, t0 * wy0);
        }
    }
}

}  // namespace

extern "C" void kernel_launch(void* const* d_in, const int* in_sizes, int n_in,
                              void* d_out, int out_size) {
    const float* x    = (const float*)d_in[0];
    const float* offs = (const float*)d_in[1];
    if (n_in >= 2 && in_sizes[0] == 2 * V) {   // tolerate swapped metadata order
        const float* t = x; x = offs; offs = t;
    }
    dim3 grid(H / TILE_Y, BCN);
    shift_views_kernel<<<grid, NTHREADS>>>(x, offs, (float*)d_out);
}